// round 10
// baseline (speedup 1.0000x reference)
#include <cuda_runtime.h>
#include <cuda_bf16.h>
#include <string.h>

// Problem constants (static shapes from the reference)
#define NPTS   32768          // 8 * 4096 points (contiguous in output)
#define NROWS  4096           // 64 * 64 (m,n) pairs
#define NBASIS 23

// Scratch: poly[k][p], k-major so GEMM-side loads are coalesced.
__device__ float g_poly[NBASIS * NPTS];

// ---------------------------------------------------------------------------
// Kernel 1: per-point hydrogen wavefunction basis (validated rel_err 1.2e-7).
// ---------------------------------------------------------------------------
__global__ void basis_kernel(const float* __restrict__ pos) {
    int p = blockIdx.x * blockDim.x + threadIdx.x;
    if (p >= NPTS) return;

    float x = pos[3 * p + 0], y = pos[3 * p + 1], z = pos[3 * p + 2];
    float r    = sqrtf(x * x + y * y + z * z) + 1e-12f;
    float invr = 1.0f / r;
    float xs = x * invr, ys = y * invr, ct = z * invr;

    float e1 = expf(-r), e2 = expf(-0.5f * r);
    float e3 = expf(-r * (1.0f / 3.0f)), e4 = expf(-0.25f * r);

    const float C00 = 0.28209479177387814f;
    const float K10 = 0.4886025119029199f;
    const float C21 = 1.0925484305920792f;
    const float C22 = 0.5462742152960396f;
    const float C20 = 0.31539156525252005f;

    float Y1m1 = -K10 * ys, Y10 = K10 * ct, Y1p1 = -K10 * xs;
    float Y2m2 =  C21 * xs * ys;
    float Y2m1 = -C21 * ys * ct;
    float Y20  =  C20 * (3.0f * ct * ct - 1.0f);
    float Y2p1 = -C21 * xs * ct;
    float Y2p2 =  C22 * (xs * xs - ys * ys);

    float R10 = 2.0f * e1;
    float R20 = 0.35355339059327373f * e2 * (2.0f - r);
    float R21 = 0.2041241452319315f  * e2 * r;

    float rho3 = (2.0f / 3.0f) * r;
    float R30 = 0.1283000598199168f   * e3 * (3.0f - 3.0f * rho3 + 0.5f * rho3 * rho3);
    float R31 = 0.045360921162019494f * e3 * rho3 * (4.0f - rho3);
    float R32 = 0.02028602242947916f  * e3 * rho3 * rho3;

    float rho4 = 0.5f * r;
    float R40 = 0.0625f * e4 *
                (4.0f - 6.0f * rho4 + 2.0f * rho4 * rho4 - rho4 * rho4 * rho4 * (1.0f / 6.0f));
    float R41 = 0.016137430609197573f * e4 * rho4 * (10.0f - 5.0f * rho4 + 0.5f * rho4 * rho4);
    float R42 = 0.004658474194686761f * e4 * rho4 * rho4 * (6.0f - rho4);

    float v[NBASIS];
    v[0]  = R10 * C00;
    v[1]  = R20 * C00;
    v[2]  = R21 * Y1m1;  v[3]  = R21 * Y10;  v[4]  = R21 * Y1p1;
    v[5]  = R30 * C00;
    v[6]  = R31 * Y1m1;  v[7]  = R31 * Y10;  v[8]  = R31 * Y1p1;
    v[9]  = R32 * Y2m2;  v[10] = R32 * Y2m1; v[11] = R32 * Y20;
    v[12] = R32 * Y2p1;  v[13] = R32 * Y2p2;
    v[14] = R40 * C00;
    v[15] = R41 * Y1m1;  v[16] = R41 * Y10;  v[17] = R41 * Y1p1;
    v[18] = R42 * Y2m2;  v[19] = R42 * Y2m1; v[20] = R42 * Y20;
    v[21] = R42 * Y2p1;  v[22] = R42 * Y2p2;

#pragma unroll
    for (int k = 0; k < NBASIS; k++) g_poly[k * NPTS + p] = v[k];
}

// ---------------------------------------------------------------------------
// Kernel 2: out(4096 x 32768) = coeff(4096 x 23) @ poly(23 x 32768)
// f32x2 GEMM, occupancy-tuned (3 CTAs/SM target, <=84 regs):
//   - row-paired accumulators: acc{r,r+1}[pt] += {c_r[k],c_{r+1}[k]} * {p,p}
//   - coeff tile k-major in smem; one LDS.128 broadcast = 4 rows' coeffs,
//     (x,y)/(z,w) halves are natural even-aligned f32x2 pairs
//   - poly kept SCALAR in regs (46 regs, not 92); {p,p} packed per use —
//     the launch-bounds reg cap stops ptxas from hoisting the dups
//   - thread's 2 points are ADJACENT -> per-row store is one STG.64
// ---------------------------------------------------------------------------
#define TPB   256
#define PT    512    // points per block (2 adjacent per thread)
#define RT    128    // coefficient rows per block

__device__ __forceinline__ float2 fma2(float2 a, float2 b, float2 c) {
    unsigned long long ua, ub, uc;
    memcpy(&ua, &a, 8); memcpy(&ub, &b, 8); memcpy(&uc, &c, 8);
    asm("fma.rn.f32x2 %0, %1, %2, %0;" : "+l"(uc) : "l"(ua), "l"(ub));
    float2 d; memcpy(&d, &uc, 8);
    return d;
}

__global__ __launch_bounds__(TPB, 3) void gemm_kernel(const float* __restrict__ coeff,
                                                      float* __restrict__ out) {
    __shared__ float cs[NBASIS * RT];   // k-major: cs[k*RT + row], 11.5 KB

    int tid = threadIdx.x;
    int p0  = blockIdx.x * PT + 2 * tid;  // two adjacent points p0, p0+1
    int r0  = blockIdx.y * RT;

    // Stage coefficient tile transposed to k-major.
    for (int i = tid; i < NBASIS * RT; i += TPB) {
        int k  = i / RT;
        int rr = i - k * RT;
        cs[i] = coeff[(r0 + rr) * NBASIS + k];
    }

    // Poly values for this thread's 2 points: SCALAR registers (46 total).
    float q0[NBASIS], q1[NBASIS];
#pragma unroll
    for (int k = 0; k < NBASIS; k++) {
        float2 t = *reinterpret_cast<const float2*>(&g_poly[k * NPTS + p0]);
        q0[k] = t.x;
        q1[k] = t.y;
    }
    __syncthreads();

    for (int rj = 0; rj < RT; rj += 4) {
        float2 a00 = make_float2(0.0f, 0.0f);   // p0, rows rj, rj+1
        float2 a01 = make_float2(0.0f, 0.0f);   // p0, rows rj+2, rj+3
        float2 a10 = make_float2(0.0f, 0.0f);   // p1, rows rj, rj+1
        float2 a11 = make_float2(0.0f, 0.0f);   // p1, rows rj+2, rj+3
#pragma unroll
        for (int k = 0; k < NBASIS; k++) {
            float4 c4 = *reinterpret_cast<const float4*>(&cs[k * RT + rj]);  // LDS.128 bc
            float2 cA = make_float2(c4.x, c4.y);   // rows rj, rj+1 (natural pair)
            float2 cB = make_float2(c4.z, c4.w);   // rows rj+2, rj+3
            float2 pp0 = make_float2(q0[k], q0[k]);  // packed per use (reg-capped)
            float2 pp1 = make_float2(q1[k], q1[k]);
            a00 = fma2(cA, pp0, a00);
            a10 = fma2(cA, pp1, a10);
            a01 = fma2(cB, pp0, a01);
            a11 = fma2(cB, pp1, a11);
        }
        // Per row: {val(p0), val(p0+1)} adjacent -> single STG.64, coalesced.
        float* ob = out + (size_t)(r0 + rj) * NPTS + p0;
        __stcs(reinterpret_cast<float2*>(ob),                    make_float2(a00.x, a10.x));
        __stcs(reinterpret_cast<float2*>(ob + (size_t)NPTS),     make_float2(a00.y, a10.y));
        __stcs(reinterpret_cast<float2*>(ob + (size_t)2 * NPTS), make_float2(a01.x, a11.x));
        __stcs(reinterpret_cast<float2*>(ob + (size_t)3 * NPTS), make_float2(a01.y, a11.y));
    }
}

// ---------------------------------------------------------------------------
// Launch: [0] position (8*4096*3 f32), [1] coefficients (64*64*23 f32).
// Output: (64,64,8,4096) f32 = out[row][point].
// ---------------------------------------------------------------------------
extern "C" void kernel_launch(void* const* d_in, const int* in_sizes, int n_in,
                              void* d_out, int out_size) {
    const float* pos   = (const float*)d_in[0];
    const float* coeff = (const float*)d_in[1];
    float* out = (float*)d_out;

    basis_kernel<<<NPTS / 256, 256>>>(pos);

    dim3 grid(NPTS / PT, NROWS / RT);   // (64, 32)
    gemm_kernel<<<grid, TPB>>>(coeff, out);
}

// round 12
// speedup vs baseline: 1.0195x; 1.0195x over previous
#include <cuda_runtime.h>
#include <cuda_bf16.h>
#include <string.h>

// Problem constants (static shapes from the reference)
#define NPTS   32768          // 8 * 4096 points (contiguous in output)
#define NROWS  4096           // 64 * 64 (m,n) pairs
#define NBASIS 23

// Scratch: poly[k][p], k-major so GEMM-side loads are coalesced.
__device__ float g_poly[NBASIS * NPTS];

// ---------------------------------------------------------------------------
// Kernel 1: per-point hydrogen wavefunction basis (validated rel_err 1.2e-7).
// ---------------------------------------------------------------------------
__global__ void basis_kernel(const float* __restrict__ pos) {
    int p = blockIdx.x * blockDim.x + threadIdx.x;
    if (p >= NPTS) return;

    float x = pos[3 * p + 0], y = pos[3 * p + 1], z = pos[3 * p + 2];
    float r    = sqrtf(x * x + y * y + z * z) + 1e-12f;
    float invr = 1.0f / r;
    float xs = x * invr, ys = y * invr, ct = z * invr;

    float e1 = expf(-r), e2 = expf(-0.5f * r);
    float e3 = expf(-r * (1.0f / 3.0f)), e4 = expf(-0.25f * r);

    const float C00 = 0.28209479177387814f;
    const float K10 = 0.4886025119029199f;
    const float C21 = 1.0925484305920792f;
    const float C22 = 0.5462742152960396f;
    const float C20 = 0.31539156525252005f;

    float Y1m1 = -K10 * ys, Y10 = K10 * ct, Y1p1 = -K10 * xs;
    float Y2m2 =  C21 * xs * ys;
    float Y2m1 = -C21 * ys * ct;
    float Y20  =  C20 * (3.0f * ct * ct - 1.0f);
    float Y2p1 = -C21 * xs * ct;
    float Y2p2 =  C22 * (xs * xs - ys * ys);

    float R10 = 2.0f * e1;
    float R20 = 0.35355339059327373f * e2 * (2.0f - r);
    float R21 = 0.2041241452319315f  * e2 * r;

    float rho3 = (2.0f / 3.0f) * r;
    float R30 = 0.1283000598199168f   * e3 * (3.0f - 3.0f * rho3 + 0.5f * rho3 * rho3);
    float R31 = 0.045360921162019494f * e3 * rho3 * (4.0f - rho3);
    float R32 = 0.02028602242947916f  * e3 * rho3 * rho3;

    float rho4 = 0.5f * r;
    float R40 = 0.0625f * e4 *
                (4.0f - 6.0f * rho4 + 2.0f * rho4 * rho4 - rho4 * rho4 * rho4 * (1.0f / 6.0f));
    float R41 = 0.016137430609197573f * e4 * rho4 * (10.0f - 5.0f * rho4 + 0.5f * rho4 * rho4);
    float R42 = 0.004658474194686761f * e4 * rho4 * rho4 * (6.0f - rho4);

    float v[NBASIS];
    v[0]  = R10 * C00;
    v[1]  = R20 * C00;
    v[2]  = R21 * Y1m1;  v[3]  = R21 * Y10;  v[4]  = R21 * Y1p1;
    v[5]  = R30 * C00;
    v[6]  = R31 * Y1m1;  v[7]  = R31 * Y10;  v[8]  = R31 * Y1p1;
    v[9]  = R32 * Y2m2;  v[10] = R32 * Y2m1; v[11] = R32 * Y20;
    v[12] = R32 * Y2p1;  v[13] = R32 * Y2p2;
    v[14] = R40 * C00;
    v[15] = R41 * Y1m1;  v[16] = R41 * Y10;  v[17] = R41 * Y1p1;
    v[18] = R42 * Y2m2;  v[19] = R42 * Y2m1; v[20] = R42 * Y20;
    v[21] = R42 * Y2p1;  v[22] = R42 * Y2p2;

#pragma unroll
    for (int k = 0; k < NBASIS; k++) g_poly[k * NPTS + p] = v[k];
}

// ---------------------------------------------------------------------------
// Kernel 2: out(4096 x 32768) = coeff(4096 x 23) @ poly(23 x 32768)
// f32x2 GEMM, fma-pipe-saturating design:
//   - row-paired accumulators: acc{r,r+1}[pt] += {c_r[k],c_{r+1}[k]} * {p,p}
//   - 16 rows per inner iter: coeff pairs read as ulonglong2 straight from
//     k-major smem (LDS.128 -> two ready 64-bit operands, ZERO pack MOVs);
//     only 4 LDS per k for 16 fma2
//   - poly dup {p,p}: 2 per k, amortized over 16 rows, forced to ALU MOV
//   - 16 independent fma2 chains; ~106 regs -> 2 CTAs/SM; STG.64 stores
// ---------------------------------------------------------------------------
#define TPB   256
#define PT    512    // points per block (2 adjacent per thread)
#define RT    128    // coefficient rows per block
#define RI    16     // rows per inner iteration

typedef unsigned long long ull;

__device__ __forceinline__ ull dup2(float v) {
    ull u;
    asm("mov.b64 %0, {%1, %1};" : "=l"(u) : "f"(v));
    return u;
}
__device__ __forceinline__ void fma2(ull& acc, ull a, ull b) {
    asm("fma.rn.f32x2 %0, %1, %2, %0;" : "+l"(acc) : "l"(a), "l"(b));
}
__device__ __forceinline__ void unpk(ull u, float& lo, float& hi) {
    asm("mov.b64 {%0, %1}, %2;" : "=f"(lo), "=f"(hi) : "l"(u));
}

__global__ __launch_bounds__(TPB, 2) void gemm_kernel(const float* __restrict__ coeff,
                                                      float* __restrict__ out) {
    __shared__ __align__(16) float cs[NBASIS * RT];   // k-major: cs[k*RT + row]

    int tid = threadIdx.x;
    int p0  = blockIdx.x * PT + 2 * tid;  // two adjacent points p0, p0+1
    int r0  = blockIdx.y * RT;

    // Stage coefficient tile transposed to k-major.
    for (int i = tid; i < NBASIS * RT; i += TPB) {
        int k  = i / RT;
        int rr = i - k * RT;
        cs[i] = coeff[(r0 + rr) * NBASIS + k];
    }

    // Poly values for this thread's 2 points: scalar registers (46 total).
    float q0[NBASIS], q1[NBASIS];
#pragma unroll
    for (int k = 0; k < NBASIS; k++) {
        float2 t = *reinterpret_cast<const float2*>(&g_poly[k * NPTS + p0]);
        q0[k] = t.x;
        q1[k] = t.y;
    }
    __syncthreads();

    for (int rj = 0; rj < RT; rj += RI) {
        ull a0[RI / 2], a1[RI / 2];    // a0[j]: p0 rows rj+2j,rj+2j+1; a1: p0+1
#pragma unroll
        for (int j = 0; j < RI / 2; j++) { a0[j] = 0ull; a1[j] = 0ull; }

#pragma unroll
        for (int k = 0; k < NBASIS; k++) {
            const ulonglong2* cp =
                reinterpret_cast<const ulonglong2*>(&cs[k * RT + rj]);
            ulonglong2 cA = cp[0];     // coeff pairs rows rj..rj+3   (LDS.128)
            ulonglong2 cB = cp[1];     // rows rj+4..rj+7
            ulonglong2 cC = cp[2];     // rows rj+8..rj+11
            ulonglong2 cD = cp[3];     // rows rj+12..rj+15
            ull pd0 = dup2(q0[k]);     // ALU MOVs, 2 per k for 16 rows
            ull pd1 = dup2(q1[k]);
            fma2(a0[0], cA.x, pd0);  fma2(a1[0], cA.x, pd1);
            fma2(a0[1], cA.y, pd0);  fma2(a1[1], cA.y, pd1);
            fma2(a0[2], cB.x, pd0);  fma2(a1[2], cB.x, pd1);
            fma2(a0[3], cB.y, pd0);  fma2(a1[3], cB.y, pd1);
            fma2(a0[4], cC.x, pd0);  fma2(a1[4], cC.x, pd1);
            fma2(a0[5], cC.y, pd0);  fma2(a1[5], cC.y, pd1);
            fma2(a0[6], cD.x, pd0);  fma2(a1[6], cD.x, pd1);
            fma2(a0[7], cD.y, pd0);  fma2(a1[7], cD.y, pd1);
        }

        // Epilogue: rows rj+2j (lo halves) and rj+2j+1 (hi halves); the two
        // adjacent points merge into one coalesced STG.64 per row.
        float* ob = out + (size_t)(r0 + rj) * NPTS + p0;
#pragma unroll
        for (int j = 0; j < RI / 2; j++) {
            float x0, y0, x1, y1;
            unpk(a0[j], x0, y0);       // point p0: rows 2j, 2j+1
            unpk(a1[j], x1, y1);       // point p0+1
            __stcs(reinterpret_cast<float2*>(ob + (size_t)(2 * j) * NPTS),
                   make_float2(x0, x1));
            __stcs(reinterpret_cast<float2*>(ob + (size_t)(2 * j + 1) * NPTS),
                   make_float2(y0, y1));
        }
    }
}

// ---------------------------------------------------------------------------
// Launch: [0] position (8*4096*3 f32), [1] coefficients (64*64*23 f32).
// Output: (64,64,8,4096) f32 = out[row][point].
// ---------------------------------------------------------------------------
extern "C" void kernel_launch(void* const* d_in, const int* in_sizes, int n_in,
                              void* d_out, int out_size) {
    const float* pos   = (const float*)d_in[0];
    const float* coeff = (const float*)d_in[1];
    float* out = (float*)d_out;

    basis_kernel<<<NPTS / 256, 256>>>(pos);

    dim3 grid(NPTS / PT, NROWS / RT);   // (64, 32)
    gemm_kernel<<<grid, TPB>>>(coeff, out);
}

// round 14
// speedup vs baseline: 1.1684x; 1.1461x over previous
#include <cuda_runtime.h>
#include <cuda_bf16.h>
#include <string.h>

// Problem constants (static shapes from the reference)
#define NPTS   32768          // 8 * 4096 points (contiguous in output)
#define NROWS  4096           // 64 * 64 (m,n) pairs
#define NBASIS 23

// Scratch: poly[k][p], k-major so GEMM-side loads are coalesced.
__device__ float g_poly[NBASIS * NPTS];

// ---------------------------------------------------------------------------
// Kernel 1: per-point hydrogen wavefunction basis (validated rel_err 1.2e-7).
// ---------------------------------------------------------------------------
__global__ void basis_kernel(const float* __restrict__ pos) {
    int p = blockIdx.x * blockDim.x + threadIdx.x;
    if (p >= NPTS) return;

    float x = pos[3 * p + 0], y = pos[3 * p + 1], z = pos[3 * p + 2];
    float r    = sqrtf(x * x + y * y + z * z) + 1e-12f;
    float invr = 1.0f / r;
    float xs = x * invr, ys = y * invr, ct = z * invr;

    float e1 = expf(-r), e2 = expf(-0.5f * r);
    float e3 = expf(-r * (1.0f / 3.0f)), e4 = expf(-0.25f * r);

    const float C00 = 0.28209479177387814f;
    const float K10 = 0.4886025119029199f;
    const float C21 = 1.0925484305920792f;
    const float C22 = 0.5462742152960396f;
    const float C20 = 0.31539156525252005f;

    float Y1m1 = -K10 * ys, Y10 = K10 * ct, Y1p1 = -K10 * xs;
    float Y2m2 =  C21 * xs * ys;
    float Y2m1 = -C21 * ys * ct;
    float Y20  =  C20 * (3.0f * ct * ct - 1.0f);
    float Y2p1 = -C21 * xs * ct;
    float Y2p2 =  C22 * (xs * xs - ys * ys);

    float R10 = 2.0f * e1;
    float R20 = 0.35355339059327373f * e2 * (2.0f - r);
    float R21 = 0.2041241452319315f  * e2 * r;

    float rho3 = (2.0f / 3.0f) * r;
    float R30 = 0.1283000598199168f   * e3 * (3.0f - 3.0f * rho3 + 0.5f * rho3 * rho3);
    float R31 = 0.045360921162019494f * e3 * rho3 * (4.0f - rho3);
    float R32 = 0.02028602242947916f  * e3 * rho3 * rho3;

    float rho4 = 0.5f * r;
    float R40 = 0.0625f * e4 *
                (4.0f - 6.0f * rho4 + 2.0f * rho4 * rho4 - rho4 * rho4 * rho4 * (1.0f / 6.0f));
    float R41 = 0.016137430609197573f * e4 * rho4 * (10.0f - 5.0f * rho4 + 0.5f * rho4 * rho4);
    float R42 = 0.004658474194686761f * e4 * rho4 * rho4 * (6.0f - rho4);

    float v[NBASIS];
    v[0]  = R10 * C00;
    v[1]  = R20 * C00;
    v[2]  = R21 * Y1m1;  v[3]  = R21 * Y10;  v[4]  = R21 * Y1p1;
    v[5]  = R30 * C00;
    v[6]  = R31 * Y1m1;  v[7]  = R31 * Y10;  v[8]  = R31 * Y1p1;
    v[9]  = R32 * Y2m2;  v[10] = R32 * Y2m1; v[11] = R32 * Y20;
    v[12] = R32 * Y2p1;  v[13] = R32 * Y2p2;
    v[14] = R40 * C00;
    v[15] = R41 * Y1m1;  v[16] = R41 * Y10;  v[17] = R41 * Y1p1;
    v[18] = R42 * Y2m2;  v[19] = R42 * Y2m1; v[20] = R42 * Y20;
    v[21] = R42 * Y2p1;  v[22] = R42 * Y2p2;

#pragma unroll
    for (int k = 0; k < NBASIS; k++) g_poly[k * NPTS + p] = v[k];
}

// ---------------------------------------------------------------------------
// Kernel 2: out(4096 x 32768) = coeff(4096 x 23) @ poly(23 x 32768)
// f32x2 GEMM, W=4 points/thread x rows-paired accumulators:
//   acc{r,r+1}[pt] += {c_r[k], c_{r+1}[k]} * {p,p}
//   - coeff pairs read DIRECTLY as ulonglong2 from k-major smem
//     (1 LDS.128 per k per 4 rows; zero packing MOVs on any pipe)
//   - W=4 halves coeff-smem bytes per output (23 B/elem, the L1 lever:
//     empirically L1% ~ 92/W B/elem across R8-R12)
//   - poly dup {p,p} via mov.b64 -> ALU pipe (4 dups : 8 fma2 per k)
//   - 4 adjacent points -> one STG.128 per row
// ---------------------------------------------------------------------------
#define TPB   256
#define PT    1024   // points per block (4 adjacent per thread)
#define RT    128    // coefficient rows per block
#define RI    4      // rows per inner iteration

typedef unsigned long long ull;

__device__ __forceinline__ ull dup2(float v) {
    ull u;
    asm("mov.b64 %0, {%1, %1};" : "=l"(u) : "f"(v));
    return u;
}
__device__ __forceinline__ void fma2(ull& acc, ull a, ull b) {
    asm("fma.rn.f32x2 %0, %1, %2, %0;" : "+l"(acc) : "l"(a), "l"(b));
}
__device__ __forceinline__ void unpk(ull u, float& lo, float& hi) {
    asm("mov.b64 {%0, %1}, %2;" : "=f"(lo), "=f"(hi) : "l"(u));
}

__global__ __launch_bounds__(TPB, 2) void gemm_kernel(const float* __restrict__ coeff,
                                                      float* __restrict__ out) {
    __shared__ __align__(16) float cs[NBASIS * RT];   // k-major: cs[k*RT + row]

    int tid = threadIdx.x;
    int p0  = blockIdx.x * PT + 4 * tid;  // four adjacent points p0..p0+3
    int r0  = blockIdx.y * RT;

    // Stage coefficient tile transposed to k-major.
    for (int i = tid; i < NBASIS * RT; i += TPB) {
        int k  = i / RT;
        int rr = i - k * RT;
        cs[i] = coeff[(r0 + rr) * NBASIS + k];
    }

    // Poly for this thread's 4 points: 23 x float4 = 92 scalar regs.
    float4 pv[NBASIS];
#pragma unroll
    for (int k = 0; k < NBASIS; k++)
        pv[k] = *reinterpret_cast<const float4*>(&g_poly[k * NPTS + p0]);
    __syncthreads();

    for (int rj = 0; rj < RT; rj += RI) {
        // a[j][i]: rows {rj+2j, rj+2j+1} for point p0+i
        ull a[2][4];
#pragma unroll
        for (int j = 0; j < 2; j++)
#pragma unroll
            for (int i = 0; i < 4; i++) a[j][i] = 0ull;

#pragma unroll
        for (int k = 0; k < NBASIS; k++) {
            ulonglong2 cp =
                *reinterpret_cast<const ulonglong2*>(&cs[k * RT + rj]);  // LDS.128
            ull d0 = dup2(pv[k].x);   // ALU MOVs: 4 per k, serve 8 fma2
            ull d1 = dup2(pv[k].y);
            ull d2 = dup2(pv[k].z);
            ull d3 = dup2(pv[k].w);
            fma2(a[0][0], cp.x, d0);  fma2(a[0][1], cp.x, d1);
            fma2(a[0][2], cp.x, d2);  fma2(a[0][3], cp.x, d3);
            fma2(a[1][0], cp.y, d0);  fma2(a[1][1], cp.y, d1);
            fma2(a[1][2], cp.y, d2);  fma2(a[1][3], cp.y, d3);
        }

        // Stores: row rj+2j   = lo halves of a[j][0..3]  -> one STG.128
        //         row rj+2j+1 = hi halves of a[j][0..3]  -> one STG.128
        float* ob = out + (size_t)(r0 + rj) * NPTS + p0;
#pragma unroll
        for (int j = 0; j < 2; j++) {
            float l0, h0, l1, h1, l2, h2, l3, h3;
            unpk(a[j][0], l0, h0);
            unpk(a[j][1], l1, h1);
            unpk(a[j][2], l2, h2);
            unpk(a[j][3], l3, h3);
            __stcs(reinterpret_cast<float4*>(ob + (size_t)(2 * j) * NPTS),
                   make_float4(l0, l1, l2, l3));
            __stcs(reinterpret_cast<float4*>(ob + (size_t)(2 * j + 1) * NPTS),
                   make_float4(h0, h1, h2, h3));
        }
    }
}

// ---------------------------------------------------------------------------
// Launch: [0] position (8*4096*3 f32), [1] coefficients (64*64*23 f32).
// Output: (64,64,8,4096) f32 = out[row][point].
// ---------------------------------------------------------------------------
extern "C" void kernel_launch(void* const* d_in, const int* in_sizes, int n_in,
                              void* d_out, int out_size) {
    const float* pos   = (const float*)d_in[0];
    const float* coeff = (const float*)d_in[1];
    float* out = (float*)d_out;

    basis_kernel<<<NPTS / 256, 256>>>(pos);

    dim3 grid(NPTS / PT, NROWS / RT);   // (32, 32)
    gemm_kernel<<<grid, TPB>>>(coeff, out);
}